// round 13
// baseline (speedup 1.0000x reference)
#include <cuda_runtime.h>
#include <cuda_bf16.h>

#define IMG    512
#define NPIX   (IMG * IMG)
#define A_W    0.3f
#define B_W    0.7f

#define TXD    16
#define TYD    16
#define RY     4             // output rows per thread
#define TILE_W 32            // 16 pairs: (c, c+16)
#define TILE_H 64            // TYD * RY
#define SH_H   70            // TILE_H + 6
#define NPAIR  22            // pair slots: logical pair base -3..18
#define S_STR  48            // floats per shared row (44 used, padded)
#define NBX    (IMG / TILE_W)   // 16
#define NBY    (IMG / TILE_H)   // 8
#define NBLK   (NBX * NBY * 64) // 8192

typedef unsigned long long ull;

__device__ float g_part[NBLK];
__device__ float g_inv;
__device__ __nv_bfloat16 g_mask_bf[64 * NPIX];   // pre-normalization mask (bf16)
// hedge if d_out only holds the first output (verified unused; kept for safety)
__device__ float g_scr_a[64 * NPIX];
__device__ float g_scr_d[64 * NPIX];

__device__ __forceinline__ ull f2add(ull a, ull b) {
    ull r; asm("add.rn.f32x2 %0, %1, %2;" : "=l"(r) : "l"(a), "l"(b)); return r;
}
__device__ __forceinline__ ull fpack(float lo, float hi) {
    ull r; asm("mov.b64 %0, {%1, %2};" : "=l"(r) : "f"(lo), "f"(hi)); return r;
}
__device__ __forceinline__ void f2unpack(ull a, float& lo, float& hi) {
    asm("mov.b64 {%0, %1}, %2;" : "=f"(lo), "=f"(hi) : "l"(a));
}
// acc += w * max(P, xc): 2 FMNMX + 1 FFMA2 (centers stay scalar)
__device__ __forceinline__ ull f2maxfma(ull w, ull P, float xl, float xh, ull acc) {
    ull r;
    asm("{\n\t"
        ".reg .f32 lo, hi;\n\t"
        ".reg .b64 u;\n\t"
        "mov.b64 {lo, hi}, %2;\n\t"
        "max.f32 lo, lo, %3;\n\t"
        "max.f32 hi, hi, %4;\n\t"
        "mov.b64 u, {lo, hi};\n\t"
        "fma.rn.f32x2 %0, %1, u, %5;\n\t"
        "}" : "=l"(r) : "l"(w), "l"(P), "f"(xl), "f"(xh), "l"(acc));
    return r;
}

__global__ __launch_bounds__(TXD * TYD, 4)
void stencil_kernel(const float* __restrict__ x, const float* __restrict__ w,
                    float* __restrict__ avg_out, float* __restrict__ diff_out)
{
    // Deinterleaved-pair tile: shared row r holds pairs (col p, col p+16) at
    // ull slot (p+3), p = -3..18. Cols 13..18 exist twice (hi of p-16, lo of p);
    // both copies are filled from the same global value.
    __shared__ __align__(16) float tile[SH_H * S_STR];
    __shared__ ull   sw2[49];
    __shared__ float red[8];
    __shared__ float s_wsum;

    const int tx  = threadIdx.x;
    const int ty  = threadIdx.y;
    const int tid = ty * TXD + tx;
    const int bx  = blockIdx.x * TILE_W;
    const int by  = blockIdx.y * TILE_H;
    const int b   = blockIdx.z;
    const float* xb = x + (size_t)b * NPIX;

    if (tid < 49) { float h = w[tid]; sw2[tid] = fpack(h, h); }
    if (tid == 0) {
        float s = 0.f;
        #pragma unroll
        for (int i = 0; i < 49; ++i) s += w[i];
        s_wsum = s;
    }

    // Fill: slot f (0..43) in row r -> logical padded col
    // L = (f>>1) - 3 + 16*(f&1); global col gx = bx + L, row gy = by + r - 3.
    for (int idx = tid; idx < SH_H * 2 * NPAIR; idx += TXD * TYD) {
        int r = idx / (2 * NPAIR);
        int f = idx - r * (2 * NPAIR);
        int L = (f >> 1) - 3 + ((f & 1) << 4);
        int gy = by + r - 3;
        int gx = bx + L;
        float v = 0.f;
        if ((unsigned)gy < IMG && (unsigned)gx < IMG) v = __ldg(&xb[gy * IMG + gx]);
        tile[r * S_STR + f] = v;
    }
    __syncthreads();

    const int r0 = ty * RY;

    // Scalar centers: pair slot tx+3 at row r0+r+3 (cols bx+tx, bx+tx+16)
    float xcl[RY], xch[RY];
    #pragma unroll
    for (int r = 0; r < RY; ++r) {
        const ull* rp = reinterpret_cast<const ull*>(&tile[(r0 + r + 3) * S_STR]);
        f2unpack(rp[tx + 3], xcl[r], xch[r]);
    }

    ull mean[RY] = {}, acc[RY] = {};

    #pragma unroll
    for (int k = 0; k < RY + 6; ++k) {
        const ull* rp = reinterpret_cast<const ull*>(&tile[(r0 + k) * S_STR]);

        ull P[7];
        #pragma unroll
        for (int m = 0; m < 7; ++m) P[m] = rp[tx + m];

        ull rs = f2add(f2add(f2add(P[0], P[1]), f2add(P[2], P[3])),
                       f2add(f2add(P[4], P[5]), P[6]));

        #pragma unroll
        for (int r = 0; r < RY; ++r) {
            const int i = k - r;                 // tap row
            if (0 <= i && i <= 6) {
                mean[r] = f2add(mean[r], rs);
                #pragma unroll
                for (int j = 0; j < 7; ++j) {
                    if (i == 3 && j == 3) continue;   // center weight = 0
                    acc[r] = f2maxfma(sw2[i * 7 + j], P[j], xcl[r], xch[r], acc[r]);
                }
            }
        }
    }

    // Epilogue: diff = acc - x*Wsum; px cols (bx+tx, bx+tx+16)
    const float wsum = s_wsum;
    float local = 0.f;
    #pragma unroll
    for (int r = 0; r < RY; ++r) {
        float m0, m1, a0, a1;
        f2unpack(mean[r], m0, m1);
        f2unpack(acc[r],  a0, a1);
        float d0 = fmaf(-wsum, xcl[r], a0);
        float d1 = fmaf(-wsum, xch[r], a1);
        float e0 = __expf(m0 * (-1.f / 49.f));
        float e1 = __expf(m1 * (-1.f / 49.f));
        float k0 = fmaf(B_W, d0, A_W * e0);
        float k1 = fmaf(B_W, d1, A_W * e1);
        local += k0 * k0 + k1 * k1;
        size_t base = (size_t)b * NPIX + (size_t)(by + r0 + r) * IMG + bx + tx;
        avg_out[base]        = e0;
        avg_out[base + 16]   = e1;
        diff_out[base]       = d0;
        diff_out[base + 16]  = d1;
        g_mask_bf[base]      = __float2bfloat16(k0);
        g_mask_bf[base + 16] = __float2bfloat16(k1);
    }

    // Block reduction -> plain store of partial (no atomics)
    #pragma unroll
    for (int s = 16; s > 0; s >>= 1)
        local += __shfl_down_sync(0xffffffffu, local, s);
    const int lane = tid & 31, warp = tid >> 5;
    if (lane == 0) red[warp] = local;
    __syncthreads();
    if (tid == 0) {
        float tot = 0.f;
        #pragma unroll
        for (int i = 0; i < 8; ++i) tot += red[i];
        g_part[blockIdx.x + NBX * (blockIdx.y + NBY * blockIdx.z)] = tot;
    }
}

__global__ __launch_bounds__(1024)
void norm_kernel()
{
    __shared__ double red[32];
    const int tid = threadIdx.x;
    double s = 0.0;
    for (int i = tid; i < NBLK; i += 1024) s += (double)g_part[i];
    #pragma unroll
    for (int sh = 16; sh > 0; sh >>= 1)
        s += __shfl_down_sync(0xffffffffu, s, sh);
    if ((tid & 31) == 0) red[tid >> 5] = s;
    __syncthreads();
    if (tid < 32) {
        double v = red[tid];
        #pragma unroll
        for (int sh = 16; sh > 0; sh >>= 1)
            v += __shfl_down_sync(0xffffffffu, v, sh);
        if (tid == 0) g_inv = rsqrtf((float)v);
    }
}

__global__ __launch_bounds__(256)
void threshold_kernel(const float* __restrict__ x, float* __restrict__ out, int n4)
{
    int i = blockIdx.x * blockDim.x + threadIdx.x;
    if (i >= n4) return;
    const float inv = g_inv;
    float4 xv = ((const float4*)x)[i];
    uint2 mraw = ((const uint2*)g_mask_bf)[i];        // 4 bf16 mask values
    float2 m01 = __bfloat1622float2(*reinterpret_cast<__nv_bfloat162*>(&mraw.x));
    float2 m23 = __bfloat1622float2(*reinterpret_cast<__nv_bfloat162*>(&mraw.y));
    float4 o;
    o.x = xv.x > m01.x * inv ? xv.x : 0.f;
    o.y = xv.y > m01.y * inv ? xv.y : 0.f;
    o.z = xv.z > m23.x * inv ? xv.z : 0.f;
    o.w = xv.w > m23.y * inv ? xv.w : 0.f;
    ((float4*)out)[i] = o;
}

extern "C" void kernel_launch(void* const* d_in, const int* in_sizes, int n_in,
                              void* d_out, int out_size)
{
    const float* x = (const float*)d_in[0];
    const float* w = (const float*)d_in[1];
    float* out = (float*)d_out;

    const int N     = in_sizes[0];          // 64*512*512
    const int batch = N / NPIX;             // 64

    float* avg_ptr;
    float* diff_ptr;
    if (out_size >= 3 * N) {                // verified layout: (out, avg, diff)
        avg_ptr  = out + N;
        diff_ptr = out + 2 * N;
    } else {
        void* pa = nullptr; void* pd = nullptr;
        cudaGetSymbolAddress(&pa, g_scr_a);
        cudaGetSymbolAddress(&pd, g_scr_d);
        avg_ptr  = (float*)pa;
        diff_ptr = (float*)pd;
    }

    dim3 grid(NBX, NBY, batch);
    dim3 block(TXD, TYD);
    stencil_kernel<<<grid, block>>>(x, w, avg_ptr, diff_ptr);

    norm_kernel<<<1, 1024>>>();

    const int n4 = N / 4;
    threshold_kernel<<<(n4 + 255) / 256, 256>>>(x, out, n4);
}

// round 14
// speedup vs baseline: 1.2710x; 1.2710x over previous
#include <cuda_runtime.h>
#include <cuda_bf16.h>

#define IMG    512
#define NPIX   (IMG * IMG)
#define A_W    0.3f
#define B_W    0.7f

#define TXD    16
#define TYD    16
#define RY     2             // output rows per thread
#define TILE_W 64
#define TILE_H 32            // TYD * RY
#define SH_H   38            // TILE_H + 6
#define NPAIR  38            // pair-columns: logical pair base -3..34
#define S_STR  88            // floats per shared row (≡8 mod 16: bank-safe across rows)
#define NBX    (IMG / TILE_W)   // 8
#define NBY    (IMG / TILE_H)   // 16
#define NBLK   (NBX * NBY * 64) // 8192

typedef unsigned long long ull;

__device__ float g_part[NBLK];
__device__ float g_inv;
__device__ __nv_bfloat16 g_mask_bf[64 * NPIX];   // pre-normalization mask (bf16)
// hedge if d_out only holds the first output (verified unused; kept for safety)
__device__ float g_scr_a[64 * NPIX];
__device__ float g_scr_d[64 * NPIX];

__device__ __forceinline__ ull f2add(ull a, ull b) {
    ull r; asm("add.rn.f32x2 %0, %1, %2;" : "=l"(r) : "l"(a), "l"(b)); return r;
}
__device__ __forceinline__ ull fpack(float lo, float hi) {
    ull r; asm("mov.b64 %0, {%1, %2};" : "=l"(r) : "f"(lo), "f"(hi)); return r;
}
__device__ __forceinline__ void f2unpack(ull a, float& lo, float& hi) {
    asm("mov.b64 {%0, %1}, %2;" : "=f"(lo), "=f"(hi) : "l"(a));
}
// acc += w * max(P, xc): 2 FMNMX + 1 FFMA2 (centers stay scalar)
__device__ __forceinline__ ull f2maxfma(ull w, ull P, float xl, float xh, ull acc) {
    ull r;
    asm("{\n\t"
        ".reg .f32 lo, hi;\n\t"
        ".reg .b64 u;\n\t"
        "mov.b64 {lo, hi}, %2;\n\t"
        "max.f32 lo, lo, %3;\n\t"
        "max.f32 hi, hi, %4;\n\t"
        "mov.b64 u, {lo, hi};\n\t"
        "fma.rn.f32x2 %0, %1, u, %5;\n\t"
        "}" : "=l"(r) : "l"(w), "l"(P), "f"(xl), "f"(xh), "l"(acc));
    return r;
}

__global__ __launch_bounds__(TXD * TYD, 4)
void stencil_kernel(const float* __restrict__ x, const float* __restrict__ w,
                    float* __restrict__ avg_out, float* __restrict__ diff_out)
{
    // Deinterleaved-pair tile: shared row r holds pairs (col p, col p+32) at
    // ull index (p+3), p = -3..34. Cols 29..34 exist twice; both copies filled.
    __shared__ __align__(16) float tile[SH_H * S_STR];
    __shared__ ull   sw2[49];
    __shared__ float red[8];
    __shared__ float s_wsum;

    const int tx  = threadIdx.x;
    const int ty  = threadIdx.y;
    const int tid = ty * TXD + tx;
    const int bx  = blockIdx.x * TILE_W;
    const int by  = blockIdx.y * TILE_H;
    const int b   = blockIdx.z;
    const float* xb = x + (size_t)b * NPIX;

    if (tid < 49) { float h = w[tid]; sw2[tid] = fpack(h, h); }
    if (tid == 0) {
        float s = 0.f;
        #pragma unroll
        for (int i = 0; i < 49; ++i) s += w[i];
        s_wsum = s;
    }

    // Fill: physical slot f (0..75) in row r -> logical padded col
    // L = (f>>1) - 3 + 32*(f&1); global col gx = bx + L, row gy = by + r - 3.
    for (int idx = tid; idx < SH_H * 2 * NPAIR; idx += TXD * TYD) {
        int r = idx / (2 * NPAIR);
        int f = idx - r * (2 * NPAIR);
        int L = (f >> 1) - 3 + ((f & 1) << 5);
        int gy = by + r - 3;
        int gx = bx + L;
        float v = 0.f;
        if ((unsigned)gy < IMG && (unsigned)gx < IMG) v = __ldg(&xb[gy * IMG + gx]);
        tile[r * S_STR + f] = v;
    }
    __syncthreads();

    const int pc0 = tx;        // q0: pair covers cols (pc0, pc0+32)
    const int pc1 = tx + 16;   // q1
    const int r0  = ty * RY;

    // Scalar centers (lo/hi of pair pcq+3 at row r0+r+3)
    float xl0[RY], xh0[RY], xl1[RY], xh1[RY];
    #pragma unroll
    for (int r = 0; r < RY; ++r) {
        const ull* rp = reinterpret_cast<const ull*>(&tile[(r0 + r + 3) * S_STR]);
        f2unpack(rp[pc0 + 3], xl0[r], xh0[r]);
        f2unpack(rp[pc1 + 3], xl1[r], xh1[r]);
    }

    ull mean[RY][2] = {}, acc[RY][2] = {};

    #pragma unroll
    for (int k = 0; k < RY + 6; ++k) {
        const ull* rp = reinterpret_cast<const ull*>(&tile[(r0 + k) * S_STR]);

        ull P0[7], P1[7];
        #pragma unroll
        for (int m = 0; m < 7; ++m) { P0[m] = rp[pc0 + m]; P1[m] = rp[pc1 + m]; }

        ull rs0 = f2add(f2add(f2add(P0[0], P0[1]), f2add(P0[2], P0[3])),
                        f2add(f2add(P0[4], P0[5]), P0[6]));
        ull rs1 = f2add(f2add(f2add(P1[0], P1[1]), f2add(P1[2], P1[3])),
                        f2add(f2add(P1[4], P1[5]), P1[6]));

        #pragma unroll
        for (int r = 0; r < RY; ++r) {
            const int i = k - r;                 // tap row
            if (0 <= i && i <= 6) {
                mean[r][0] = f2add(mean[r][0], rs0);
                mean[r][1] = f2add(mean[r][1], rs1);
                #pragma unroll
                for (int j = 0; j < 7; ++j) {
                    if (i == 3 && j == 3) continue;   // center weight = 0
                    const ull w2 = sw2[i * 7 + j];
                    acc[r][0] = f2maxfma(w2, P0[j], xl0[r], xh0[r], acc[r][0]);
                    acc[r][1] = f2maxfma(w2, P1[j], xl1[r], xh1[r], acc[r][1]);
                }
            }
        }
    }

    // Epilogue: diff = acc - x*Wsum; px columns (pc0, pc0+32, pc1, pc1+32)
    const float wsum = s_wsum;
    float local = 0.f;
    #pragma unroll
    for (int r = 0; r < RY; ++r) {
        float mm[4], aaq[4], xc[4];
        f2unpack(mean[r][0], mm[0], mm[1]);
        f2unpack(mean[r][1], mm[2], mm[3]);
        f2unpack(acc[r][0], aaq[0], aaq[1]);
        f2unpack(acc[r][1], aaq[2], aaq[3]);
        xc[0] = xl0[r]; xc[1] = xh0[r]; xc[2] = xl1[r]; xc[3] = xh1[r];
        size_t base = (size_t)b * NPIX + (size_t)(by + r0 + r) * IMG + bx;
        const int cols[4] = { pc0, pc0 + 32, pc1, pc1 + 32 };
        #pragma unroll
        for (int c = 0; c < 4; ++c) {
            float dd = fmaf(-wsum, xc[c], aaq[c]);   // Σw·max(s,x) − x·Σw
            float a  = __expf(mm[c] * (-1.f / 49.f));
            float kk = fmaf(B_W, dd, A_W * a);
            local += kk * kk;
            avg_out[base + cols[c]]   = a;
            diff_out[base + cols[c]]  = dd;
            g_mask_bf[base + cols[c]] = __float2bfloat16(kk);
        }
    }

    // Block reduction -> plain store of partial (no atomics)
    #pragma unroll
    for (int s = 16; s > 0; s >>= 1)
        local += __shfl_down_sync(0xffffffffu, local, s);
    const int lane = tid & 31, warp = tid >> 5;
    if (lane == 0) red[warp] = local;
    __syncthreads();
    if (tid == 0) {
        float tot = 0.f;
        #pragma unroll
        for (int i = 0; i < 8; ++i) tot += red[i];
        g_part[blockIdx.x + NBX * (blockIdx.y + NBY * blockIdx.z)] = tot;
    }
}

__global__ __launch_bounds__(1024)
void norm_kernel()
{
    __shared__ double red[32];
    const int tid = threadIdx.x;
    double s = 0.0;
    for (int i = tid; i < NBLK; i += 1024) s += (double)g_part[i];
    #pragma unroll
    for (int sh = 16; sh > 0; sh >>= 1)
        s += __shfl_down_sync(0xffffffffu, s, sh);
    if ((tid & 31) == 0) red[tid >> 5] = s;
    __syncthreads();
    if (tid < 32) {
        double v = red[tid];
        #pragma unroll
        for (int sh = 16; sh > 0; sh >>= 1)
            v += __shfl_down_sync(0xffffffffu, v, sh);
        if (tid == 0) g_inv = rsqrtf((float)v);
    }
}

__global__ __launch_bounds__(256)
void threshold_kernel(const float* __restrict__ x, float* __restrict__ out, int n4)
{
    int i = blockIdx.x * blockDim.x + threadIdx.x;
    if (i >= n4) return;
    const float inv = g_inv;
    float4 xv = ((const float4*)x)[i];
    uint2 mraw = ((const uint2*)g_mask_bf)[i];        // 4 bf16 mask values
    float2 m01 = __bfloat1622float2(*reinterpret_cast<__nv_bfloat162*>(&mraw.x));
    float2 m23 = __bfloat1622float2(*reinterpret_cast<__nv_bfloat162*>(&mraw.y));
    float4 o;
    o.x = xv.x > m01.x * inv ? xv.x : 0.f;
    o.y = xv.y > m01.y * inv ? xv.y : 0.f;
    o.z = xv.z > m23.x * inv ? xv.z : 0.f;
    o.w = xv.w > m23.y * inv ? xv.w : 0.f;
    ((float4*)out)[i] = o;
}

extern "C" void kernel_launch(void* const* d_in, const int* in_sizes, int n_in,
                              void* d_out, int out_size)
{
    const float* x = (const float*)d_in[0];
    const float* w = (const float*)d_in[1];
    float* out = (float*)d_out;

    const int N     = in_sizes[0];          // 64*512*512
    const int batch = N / NPIX;             // 64

    float* avg_ptr;
    float* diff_ptr;
    if (out_size >= 3 * N) {                // verified layout: (out, avg, diff)
        avg_ptr  = out + N;
        diff_ptr = out + 2 * N;
    } else {
        void* pa = nullptr; void* pd = nullptr;
        cudaGetSymbolAddress(&pa, g_scr_a);
        cudaGetSymbolAddress(&pd, g_scr_d);
        avg_ptr  = (float*)pa;
        diff_ptr = (float*)pd;
    }

    dim3 grid(NBX, NBY, batch);
    dim3 block(TXD, TYD);
    stencil_kernel<<<grid, block>>>(x, w, avg_ptr, diff_ptr);

    norm_kernel<<<1, 1024>>>();

    const int n4 = N / 4;
    threshold_kernel<<<(n4 + 255) / 256, 256>>>(x, out, n4);
}

// round 17
// speedup vs baseline: 1.3354x; 1.0507x over previous
#include <cuda_runtime.h>
#include <cuda_bf16.h>

#define IMG    512
#define NPIX   (IMG * IMG)
#define A_W    0.3f
#define B_W    0.7f

#define TXD    16
#define TYD    16
#define RY     2             // output rows per thread
#define TILE_W 64
#define TILE_H 32            // TYD * RY
#define SH_H   38            // TILE_H + 6
#define NQUAD  22            // quad slots: logical base col -3..18, deinterleave 16
#define S_STR  88            // floats per shared row = 22 quads (16B aligned)
#define NBX    (IMG / TILE_W)   // 8
#define NBY    (IMG / TILE_H)   // 16
#define NBLK   (NBX * NBY * 64) // 8192

typedef unsigned long long ull;

__device__ float g_part[NBLK];
__device__ float g_inv;
__device__ __nv_bfloat16 g_mask_bf[64 * NPIX];   // pre-normalization mask (bf16)
// hedge if d_out only holds the first output (verified unused; kept for safety)
__device__ float g_scr_a[64 * NPIX];
__device__ float g_scr_d[64 * NPIX];

__device__ __forceinline__ ull f2add(ull a, ull b) {
    ull r; asm("add.rn.f32x2 %0, %1, %2;" : "=l"(r) : "l"(a), "l"(b)); return r;
}
__device__ __forceinline__ ull fpack(float lo, float hi) {
    ull r; asm("mov.b64 %0, {%1, %2};" : "=l"(r) : "f"(lo), "f"(hi)); return r;
}
__device__ __forceinline__ void f2unpack(ull a, float& lo, float& hi) {
    asm("mov.b64 {%0, %1}, %2;" : "=f"(lo), "=f"(hi) : "l"(a));
}
// acc += w * relu(t): per-half FMNMX, packed FFMA2 (R9-proven form)
__device__ __forceinline__ ull f2relufma(ull w, ull t, ull acc) {
    ull r;
    asm("{\n\t"
        ".reg .f32 lo, hi;\n\t"
        ".reg .b64 u;\n\t"
        "mov.b64 {lo, hi}, %2;\n\t"
        "max.f32 lo, lo, 0f00000000;\n\t"
        "max.f32 hi, hi, 0f00000000;\n\t"
        "mov.b64 u, {lo, hi};\n\t"
        "fma.rn.f32x2 %0, %1, u, %3;\n\t"
        "}" : "=l"(r) : "l"(w), "l"(t), "l"(acc));
    return r;
}

__global__ __launch_bounds__(TXD * TYD, 4)
void stencil_kernel(const float* __restrict__ x, const float* __restrict__ w,
                    float* __restrict__ avg_out, float* __restrict__ diff_out)
{
    // Quad-deinterleaved tile: row r, quad slot q (0..21) holds logical cols
    // (q-3, q-3+16, q-3+32, q-3+48). Overlapping cols stored multiple times;
    // all copies filled from the same global value.
    __shared__ __align__(16) float tile[SH_H * S_STR];
    __shared__ ull   sw2[49];
    __shared__ float red[8];

    const int tx  = threadIdx.x;
    const int ty  = threadIdx.y;
    const int tid = ty * TXD + tx;
    const int bx  = blockIdx.x * TILE_W;
    const int by  = blockIdx.y * TILE_H;
    const int b   = blockIdx.z;
    const float* xb = x + (size_t)b * NPIX;

    if (tid < 49) { float h = w[tid]; sw2[tid] = fpack(h, h); }

    // Fill: float index f (0..87) in row r -> quad q=f>>2, lane l=f&3,
    // logical padded col L = q-3+16*l; gx = bx+L, gy = by+r-3; zero OOB.
    for (int idx = tid; idx < SH_H * S_STR; idx += TXD * TYD) {
        int r = idx / S_STR;
        int f = idx - r * S_STR;
        int L = (f >> 2) - 3 + ((f & 3) << 4);
        int gy = by + r - 3;
        int gx = bx + L;
        float v = 0.f;
        if ((unsigned)gy < IMG && (unsigned)gx < IMG) v = __ldg(&xb[gy * IMG + gx]);
        tile[r * S_STR + f] = v;
    }
    __syncthreads();

    const int r0 = ty * RY;

    // Packed negated centers: quad slot tx+3, row r0+r+3.
    // pair A = cols (tx, tx+16), pair B = cols (tx+32, tx+48).
    ull nxA[RY], nxB[RY];
    #pragma unroll
    for (int r = 0; r < RY; ++r) {
        const ulonglong2* rp =
            reinterpret_cast<const ulonglong2*>(&tile[(r0 + r + 3) * S_STR]);
        ulonglong2 U = rp[tx + 3];
        float a0, a1;
        f2unpack(U.x, a0, a1); nxA[r] = fpack(-a0, -a1);
        f2unpack(U.y, a0, a1); nxB[r] = fpack(-a0, -a1);
    }

    ull mean[RY][2] = {}, diff[RY][2] = {};

    #pragma unroll
    for (int k = 0; k < RY + 6; ++k) {
        const ulonglong2* rp =
            reinterpret_cast<const ulonglong2*>(&tile[(r0 + k) * S_STR]);

        ull A[7], B[7];
        #pragma unroll
        for (int m = 0; m < 7; ++m) {
            ulonglong2 U = rp[tx + m];
            A[m] = U.x; B[m] = U.y;
        }

        ull rsA = f2add(f2add(f2add(A[0], A[1]), f2add(A[2], A[3])),
                        f2add(f2add(A[4], A[5]), A[6]));
        ull rsB = f2add(f2add(f2add(B[0], B[1]), f2add(B[2], B[3])),
                        f2add(f2add(B[4], B[5]), B[6]));

        #pragma unroll
        for (int r = 0; r < RY; ++r) {
            const int i = k - r;                 // tap row
            if (0 <= i && i <= 6) {
                mean[r][0] = f2add(mean[r][0], rsA);
                mean[r][1] = f2add(mean[r][1], rsB);
                #pragma unroll
                for (int j = 0; j < 7; ++j) {
                    if (i == 3 && j == 3) continue;   // center: relu(0)=0, w=0
                    const ull w2 = sw2[i * 7 + j];
                    diff[r][0] = f2relufma(w2, f2add(A[j], nxA[r]), diff[r][0]);
                    diff[r][1] = f2relufma(w2, f2add(B[j], nxB[r]), diff[r][1]);
                }
            }
        }
    }

    // Epilogue: px columns (tx, tx+16, tx+32, tx+48); coalesced per 16-lane group.
    float local = 0.f;
    #pragma unroll
    for (int r = 0; r < RY; ++r) {
        float mm[4], dd[4];
        f2unpack(mean[r][0], mm[0], mm[1]);
        f2unpack(mean[r][1], mm[2], mm[3]);
        f2unpack(diff[r][0], dd[0], dd[1]);
        f2unpack(diff[r][1], dd[2], dd[3]);
        size_t base = (size_t)b * NPIX + (size_t)(by + r0 + r) * IMG + bx;
        const int cols[4] = { tx, tx + 16, tx + 32, tx + 48 };
        #pragma unroll
        for (int c = 0; c < 4; ++c) {
            float a  = __expf(mm[c] * (-1.f / 49.f));
            float kk = fmaf(B_W, dd[c], A_W * a);
            local += kk * kk;
            avg_out[base + cols[c]]   = a;
            diff_out[base + cols[c]]  = dd[c];
            g_mask_bf[base + cols[c]] = __float2bfloat16(kk);
        }
    }

    // Block reduction -> plain store of partial (no atomics)
    #pragma unroll
    for (int s = 16; s > 0; s >>= 1)
        local += __shfl_down_sync(0xffffffffu, local, s);
    const int lane = tid & 31, warp = tid >> 5;
    if (lane == 0) red[warp] = local;
    __syncthreads();
    if (tid == 0) {
        float tot = 0.f;
        #pragma unroll
        for (int i = 0; i < 8; ++i) tot += red[i];
        g_part[blockIdx.x + NBX * (blockIdx.y + NBY * blockIdx.z)] = tot;
    }
}

__global__ __launch_bounds__(1024)
void norm_kernel()
{
    __shared__ double red[32];
    const int tid = threadIdx.x;
    double s = 0.0;
    for (int i = tid; i < NBLK; i += 1024) s += (double)g_part[i];
    #pragma unroll
    for (int sh = 16; sh > 0; sh >>= 1)
        s += __shfl_down_sync(0xffffffffu, s, sh);
    if ((tid & 31) == 0) red[tid >> 5] = s;
    __syncthreads();
    if (tid < 32) {
        double v = red[tid];
        #pragma unroll
        for (int sh = 16; sh > 0; sh >>= 1)
            v += __shfl_down_sync(0xffffffffu, v, sh);
        if (tid == 0) g_inv = rsqrtf((float)v);
    }
}

__global__ __launch_bounds__(256)
void threshold_kernel(const float* __restrict__ x, float* __restrict__ out, int n4)
{
    int i = blockIdx.x * blockDim.x + threadIdx.x;
    if (i >= n4) return;
    const float inv = g_inv;
    float4 xv = ((const float4*)x)[i];
    uint2 mraw = ((const uint2*)g_mask_bf)[i];        // 4 bf16 mask values
    float2 m01 = __bfloat1622float2(*reinterpret_cast<__nv_bfloat162*>(&mraw.x));
    float2 m23 = __bfloat1622float2(*reinterpret_cast<__nv_bfloat162*>(&mraw.y));
    float4 o;
    o.x = xv.x > m01.x * inv ? xv.x : 0.f;
    o.y = xv.y > m01.y * inv ? xv.y : 0.f;
    o.z = xv.z > m23.x * inv ? xv.z : 0.f;
    o.w = xv.w > m23.y * inv ? xv.w : 0.f;
    ((float4*)out)[i] = o;
}

extern "C" void kernel_launch(void* const* d_in, const int* in_sizes, int n_in,
                              void* d_out, int out_size)
{
    const float* x = (const float*)d_in[0];
    const float* w = (const float*)d_in[1];
    float* out = (float*)d_out;

    const int N     = in_sizes[0];          // 64*512*512
    const int batch = N / NPIX;             // 64

    float* avg_ptr;
    float* diff_ptr;
    if (out_size >= 3 * N) {                // verified layout: (out, avg, diff)
        avg_ptr  = out + N;
        diff_ptr = out + 2 * N;
    } else {
        void* pa = nullptr; void* pd = nullptr;
        cudaGetSymbolAddress(&pa, g_scr_a);
        cudaGetSymbolAddress(&pd, g_scr_d);
        avg_ptr  = (float*)pa;
        diff_ptr = (float*)pd;
    }

    dim3 grid(NBX, NBY, batch);
    dim3 block(TXD, TYD);
    stencil_kernel<<<grid, block>>>(x, w, avg_ptr, diff_ptr);

    norm_kernel<<<1, 1024>>>();

    const int n4 = N / 4;
    threshold_kernel<<<(n4 + 255) / 256, 256>>>(x, out, n4);
}